// round 14
// baseline (speedup 1.0000x reference)
#include <cuda_runtime.h>
#include <math.h>

// BezierRenderer: 16 batches, 512x512, 10 segments. SINGLE kernel, NO barrier,
// NO shared memory. Grid (8,16,16) = 2048 blocks, 256 threads. Tile 64x32 px;
// each thread owns 8 px: float4 at (x,y) and (x,y+16).
// EVERY warp redundantly computes the per-block setup (stroke points via
// exp2f, lane j owns segment j, cull via ballot); the render loop broadcasts
// segment params with __shfl_sync. Clamps via __saturatef (.SAT modifier).

#define NSEG  10
#define SIZEI 512

__global__ void __launch_bounds__(256)
bezier_kernel(const float* __restrict__ traj,
              const float* __restrict__ thk,
              float* __restrict__ out)
{
    const int b   = blockIdx.z;
    const int tid = threadIdx.x;
    const int tx  = blockIdx.x;         // 0..7   (64 px wide)
    const int ty  = blockIdx.y;         // 0..15  (32 px tall)

    const int x  = (tx << 6) + (tid & 15) * 4;
    const int y0 = (ty << 5) + (tid >> 4);           // rows y0 and y0+16
    float* outp0 = out + ((size_t)b << 18) + ((size_t)y0 << 9) + x;
    float* outp1 = outp0 + 16 * SIZEI;

    // Speculative zero fill — issues immediately, no dependencies.
    const float4 z = make_float4(0.f, 0.f, 0.f, 0.f);
    *reinterpret_cast<float4*>(outp0) = z;
    *reinterpret_cast<float4*>(outp1) = z;

    // ---- per-warp setup (all warps, no barrier) ----
    const int lane = tid & 31;

    const float4 tyv = __ldg(reinterpret_cast<const float4*>(traj + b * 8));
    const float4 txv = __ldg(reinterpret_cast<const float4*>(traj + b * 8 + 4));
    const float4 tkv = __ldg(reinterpret_cast<const float4*>(thk + b * 4));

    // thick = 2 * sum(thk*2 + 0.5) over 4 ctrl
    const float thick    = ((tkv.x + tkv.y + tkv.z + tkv.w) * 2.f + 2.f) * 2.f;
    const float invthick = 1.f / thick;

    // Stroke point for this lane. Lanes 0..9: gaussian-weighted sample,
    // W[p][i] = 0.75*exp(-0.125*n_i^2), n_i = p - {-0.5,3.5,6.5,9.5}.
    // exp(-0.125 n^2) == exp2(-0.18033688 n^2).
    float py, px;
    if (lane < NSEG) {
        const float p  = (float)lane;
        const float n0 = p + 0.5f, n1 = p - 3.5f, n2 = p - 6.5f, n3 = p - 9.5f;
        const float C  = -0.18033688f;    // -0.125 * log2(e)
        const float w0 = 0.75f * exp2f(C * n0 * n0);
        const float w1 = 0.75f * exp2f(C * n1 * n1);
        const float w2 = 0.75f * exp2f(C * n2 * n2);
        const float w3 = 0.75f * exp2f(C * n3 * n3);
        py = (w0 * tyv.x + w1 * tyv.y + w2 * tyv.z + w3 * tyv.w) * 512.f;
        px = (w0 * txv.x + w1 * txv.y + w2 * txv.z + w3 * txv.w) * 512.f;
    } else {                              // appended last point
        py = tyv.w * 512.f;
        px = txv.w * 512.f;
    }

    // Segment j: point j -> j+1 (from lane j+1 via shfl). Lane j owns seg j.
    const float py1 = __shfl_down_sync(0xFFFFFFFFu, py, 1);
    const float px1 = __shfl_down_sync(0xFFFFFFFFu, px, 1);
    const float dy  = py1 - py;
    const float dx  = px1 - px;
    const float id2 = 1.f / (dy * dy + dx * dx + 1e-5f);

    // Cull segment `lane` against this 64x32 tile: center
    // (tx*64+31.5, ty*32+15.5); max pixel-to-center distance
    // sqrt(31.5^2+15.5^2) = 35.11 < 35.2.
    {
        const float cx = (float)(tx << 6) + 31.5f;
        const float cy = (float)(ty << 5) + 15.5f;
        const float lim = thick + 35.2f;
        const float ay = cy - py;
        const float ax = cx - px;
        const float dotc = ay * dy + ax * dx;
        const float t   = __saturatef(dotc * id2);
        const float ry  = fmaf(-t, dy, ay);
        const float rx  = fmaf(-t, dx, ax);
        const bool  act = (lane < NSEG) && (fmaf(ry, ry, rx * rx) < lim * lim);
        unsigned int mask = __ballot_sync(0xFFFFFFFFu, act);

        if (mask == 0) return;                 // zeros already stored

        const float yf0 = (float)y0;
        const float yf1 = (float)(y0 + 16);
        const float x0  = (float)x;

        float a0 = 1e30f, a1 = 1e30f, a2 = 1e30f, a3 = 1e30f;   // row y0
        float b0 = 1e30f, b1 = 1e30f, b2 = 1e30f, b3 = 1e30f;   // row y0+16

        while (mask) {
            const int j = __ffs((int)mask) - 1;
            mask &= mask - 1;

            // Broadcast segment j's params from lane j.
            const float vjy = __shfl_sync(0xFFFFFFFFu, py, j);
            const float vjx = __shfl_sync(0xFFFFFFFFu, px, j);
            const float djy = __shfl_sync(0xFFFFFFFFu, dy, j);
            const float djx = __shfl_sync(0xFFFFFFFFu, dx, j);
            const float ij  = __shfl_sync(0xFFFFFFFFu, id2, j);

            const float ayA  = yf0 - vjy;
            const float ayB  = yf1 - vjy;
            const float cydA = ayA * djy;
            const float cydB = ayB * djy;

#pragma unroll
            for (int c = 0; c < 4; c++) {
                const float pvx = (x0 + (float)c) - vjx;
                const float pd  = pvx * djx;
                // row A
                {
                    float t  = __saturatef((pd + cydA) * ij);
                    float ry = fmaf(-t, djy, ayA);
                    float rx = fmaf(-t, djx, pvx);
                    float dd = fmaf(ry, ry, rx * rx);
                    if (c == 0) a0 = fminf(a0, dd);
                    if (c == 1) a1 = fminf(a1, dd);
                    if (c == 2) a2 = fminf(a2, dd);
                    if (c == 3) a3 = fminf(a3, dd);
                }
                // row B
                {
                    float t  = __saturatef((pd + cydB) * ij);
                    float ry = fmaf(-t, djy, ayB);
                    float rx = fmaf(-t, djx, pvx);
                    float dd = fmaf(ry, ry, rx * rx);
                    if (c == 0) b0 = fminf(b0, dd);
                    if (c == 1) b1 = fminf(b1, dd);
                    if (c == 2) b2 = fminf(b2, dd);
                    if (c == 3) b3 = fminf(b3, dd);
                }
            }
        }

        float4 r0, r1;
        r0.x = __saturatef((thick - sqrtf(a0)) * invthick);
        r0.y = __saturatef((thick - sqrtf(a1)) * invthick);
        r0.z = __saturatef((thick - sqrtf(a2)) * invthick);
        r0.w = __saturatef((thick - sqrtf(a3)) * invthick);
        r1.x = __saturatef((thick - sqrtf(b0)) * invthick);
        r1.y = __saturatef((thick - sqrtf(b1)) * invthick);
        r1.z = __saturatef((thick - sqrtf(b2)) * invthick);
        r1.w = __saturatef((thick - sqrtf(b3)) * invthick);

        *reinterpret_cast<float4*>(outp0) = r0;
        *reinterpret_cast<float4*>(outp1) = r1;
    }
}

extern "C" void kernel_launch(void* const* d_in, const int* in_sizes, int n_in,
                              void* d_out, int out_size)
{
    const float* traj = (const float*)d_in[0];   // (16, 2, 4)
    const float* thk  = (const float*)d_in[1];   // (16, 1, 4)
    float* out = (float*)d_out;                  // (16, 512, 512)

    dim3 grid(8, 16, 16);                        // 2048 blocks
    bezier_kernel<<<grid, 256>>>(traj, thk, out);
}

// round 15
// speedup vs baseline: 1.1073x; 1.1073x over previous
#include <cuda_runtime.h>
#include <math.h>

// BezierRenderer: 16 batches, 512x512, 10 segments. SINGLE kernel, NO barrier,
// NO shared memory. Grid (16,8,16) = 2048 blocks (batch fastest for SM load
// balance), 256 threads. Tile 64x32 px; each thread owns 8 px: float4 at
// (x,y) and (x,y+16). Every warp redundantly computes the per-block setup;
// render loop broadcasts segment params via __shfl_sync and uses FFMA.SAT
// (t = saturate(pvx*e + f)) for a 6-op per-pixel chain.

#define NSEG  10
#define SIZEI 512

__global__ void __launch_bounds__(256)
bezier_kernel(const float* __restrict__ traj,
              const float* __restrict__ thk,
              float* __restrict__ out)
{
    const int b   = blockIdx.x;         // 0..15 (fastest -> decorrelated activity)
    const int tx  = blockIdx.y;         // 0..7   (64 px wide)
    const int ty  = blockIdx.z;         // 0..15  (32 px tall)
    const int tid = threadIdx.x;

    const int x  = (tx << 6) + (tid & 15) * 4;
    const int y0 = (ty << 5) + (tid >> 4);           // rows y0 and y0+16
    float* outp0 = out + ((size_t)b << 18) + ((size_t)y0 << 9) + x;
    float* outp1 = outp0 + 16 * SIZEI;

    // Speculative zero fill — issues immediately, no dependencies.
    const float4 z = make_float4(0.f, 0.f, 0.f, 0.f);
    *reinterpret_cast<float4*>(outp0) = z;
    *reinterpret_cast<float4*>(outp1) = z;

    // ---- per-warp setup (all warps, no barrier) ----
    const int lane = tid & 31;

    const float4 tyv = __ldg(reinterpret_cast<const float4*>(traj + b * 8));
    const float4 txv = __ldg(reinterpret_cast<const float4*>(traj + b * 8 + 4));
    const float4 tkv = __ldg(reinterpret_cast<const float4*>(thk + b * 4));

    // thick = 2 * sum(thk*2 + 0.5) over 4 ctrl
    const float thick    = ((tkv.x + tkv.y + tkv.z + tkv.w) * 2.f + 2.f) * 2.f;
    const float invthick = 1.f / thick;

    // Stroke point for this lane. Lanes 0..9: gaussian-weighted sample,
    // W[p][i] = 0.75*exp(-0.125*n_i^2), n_i = p - {-0.5,3.5,6.5,9.5}.
    // exp(-0.125 n^2) == exp2(-0.18033688 n^2).
    float py, px;
    if (lane < NSEG) {
        const float p  = (float)lane;
        const float n0 = p + 0.5f, n1 = p - 3.5f, n2 = p - 6.5f, n3 = p - 9.5f;
        const float C  = -0.18033688f;    // -0.125 * log2(e)
        const float w0 = 0.75f * exp2f(C * n0 * n0);
        const float w1 = 0.75f * exp2f(C * n1 * n1);
        const float w2 = 0.75f * exp2f(C * n2 * n2);
        const float w3 = 0.75f * exp2f(C * n3 * n3);
        py = (w0 * tyv.x + w1 * tyv.y + w2 * tyv.z + w3 * tyv.w) * 512.f;
        px = (w0 * txv.x + w1 * txv.y + w2 * txv.z + w3 * txv.w) * 512.f;
    } else {                              // appended last point
        py = tyv.w * 512.f;
        px = txv.w * 512.f;
    }

    // Segment j: point j -> j+1 (from lane j+1 via shfl). Lane j owns seg j.
    const float py1 = __shfl_down_sync(0xFFFFFFFFu, py, 1);
    const float px1 = __shfl_down_sync(0xFFFFFFFFu, px, 1);
    const float dy  = py1 - py;
    const float dx  = px1 - px;
    const float id2 = 1.f / (dy * dy + dx * dx + 1e-5f);

    // Cull segment `lane` against this 64x32 tile: center
    // (tx*64+31.5, ty*32+15.5); max pixel-to-center distance
    // sqrt(31.5^2+15.5^2) = 35.11 < 35.2.
    const float cx = (float)(tx << 6) + 31.5f;
    const float cy = (float)(ty << 5) + 15.5f;
    const float lim = thick + 35.2f;
    const float ayc = cy - py;
    const float axc = cx - px;
    const float dotc = ayc * dy + axc * dx;
    const float tc  = __saturatef(dotc * id2);
    const float ryc = fmaf(-tc, dy, ayc);
    const float rxc = fmaf(-tc, dx, axc);
    const bool  act = (lane < NSEG) && (fmaf(ryc, ryc, rxc * rxc) < lim * lim);
    unsigned int mask = __ballot_sync(0xFFFFFFFFu, act);

    if (mask == 0) return;                 // zeros already stored

    const float yf0 = (float)y0;
    const float yf1 = (float)(y0 + 16);
    const float x0  = (float)x;

    float a0 = 1e30f, a1 = 1e30f, a2 = 1e30f, a3 = 1e30f;   // row y0
    float b0 = 1e30f, b1 = 1e30f, b2 = 1e30f, b3 = 1e30f;   // row y0+16

    while (mask) {
        const int j = __ffs((int)mask) - 1;
        mask &= mask - 1;

        // Broadcast segment j's params from lane j.
        const float vjy = __shfl_sync(0xFFFFFFFFu, py, j);
        const float vjx = __shfl_sync(0xFFFFFFFFu, px, j);
        const float djy = __shfl_sync(0xFFFFFFFFu, dy, j);
        const float djx = __shfl_sync(0xFFFFFFFFu, dx, j);
        const float ij  = __shfl_sync(0xFFFFFFFFu, id2, j);

        // t = saturate((pv . d) * ij) = saturate(pvx*e + f[row])
        const float e    = ij * djx;
        const float ayA  = yf0 - vjy;
        const float ayB  = yf1 - vjy;
        const float fA   = ayA * djy * ij;
        const float fB   = ayB * djy * ij;
        const float pvx0 = x0 - vjx;

#pragma unroll
        for (int c = 0; c < 4; c++) {
            const float pvx = pvx0 + (float)c;
            // row A
            {
                float t  = __saturatef(fmaf(pvx, e, fA));   // FFMA.SAT
                float ry = fmaf(-t, djy, ayA);
                float rx = fmaf(-t, djx, pvx);
                float dd = fmaf(ry, ry, rx * rx);
                if (c == 0) a0 = fminf(a0, dd);
                if (c == 1) a1 = fminf(a1, dd);
                if (c == 2) a2 = fminf(a2, dd);
                if (c == 3) a3 = fminf(a3, dd);
            }
            // row B
            {
                float t  = __saturatef(fmaf(pvx, e, fB));
                float ry = fmaf(-t, djy, ayB);
                float rx = fmaf(-t, djx, pvx);
                float dd = fmaf(ry, ry, rx * rx);
                if (c == 0) b0 = fminf(b0, dd);
                if (c == 1) b1 = fminf(b1, dd);
                if (c == 2) b2 = fminf(b2, dd);
                if (c == 3) b3 = fminf(b3, dd);
            }
        }
    }

    float4 r0, r1;
    r0.x = __saturatef((thick - sqrtf(a0)) * invthick);
    r0.y = __saturatef((thick - sqrtf(a1)) * invthick);
    r0.z = __saturatef((thick - sqrtf(a2)) * invthick);
    r0.w = __saturatef((thick - sqrtf(a3)) * invthick);
    r1.x = __saturatef((thick - sqrtf(b0)) * invthick);
    r1.y = __saturatef((thick - sqrtf(b1)) * invthick);
    r1.z = __saturatef((thick - sqrtf(b2)) * invthick);
    r1.w = __saturatef((thick - sqrtf(b3)) * invthick);

    *reinterpret_cast<float4*>(outp0) = r0;
    *reinterpret_cast<float4*>(outp1) = r1;
}

extern "C" void kernel_launch(void* const* d_in, const int* in_sizes, int n_in,
                              void* d_out, int out_size)
{
    const float* traj = (const float*)d_in[0];   // (16, 2, 4)
    const float* thk  = (const float*)d_in[1];   // (16, 1, 4)
    float* out = (float*)d_out;                  // (16, 512, 512)

    dim3 grid(16, 8, 16);                        // 2048 blocks, batch fastest
    bezier_kernel<<<grid, 256>>>(traj, thk, out);
}